// round 3
// baseline (speedup 1.0000x reference)
#include <cuda_runtime.h>
#include <cuda_bf16.h>
#include <cstdint>

// LaplacianLoss: out[b] = ||w * (L @ x[b])||_F * NV
//   L: [NV, NV] f32 (400 MB, streamed once; mesh Laplacian -> ~13 nz/row)
//   x: [8, NV, 3] f32  -> repacked to X[c][j], c = 3*b + k (24 channels)
//   out: 8 f32
//
// v3: float4 L stream (LDG.128) with depth-4 register pipeline; OOB handled by
// ADDRESS select into a zero buffer (no select on load results -> full MLP).
// Two-level warp-uniform zero-skip of the FMA work. Swizzled X smem layout
// for conflict-free LDS.128. Deterministic, no atomics, no allocations.

#define NVTX     10000
#define NCH      24            // 8 batches * 3 dims
#define JHALF    5000          // j range per grid.y slice
#define JT       512           // j tile staged in smem
#define RPW      4             // rows per warp
#define WARPS    8
#define ROWS_CTA (WARPS * RPW) // 32
#define NRB      ((NVTX + ROWS_CTA - 1) / ROWS_CTA) // 313
#define PD       4             // prefetch depth (128-j steps)
#define NSTEPS   40            // ceil(JHALF / 128)
#define NTILES   10            // NSTEPS / (JT/128)

typedef unsigned long long ull;

// X repacked as [6][NV] float4: quad q holds channels 4q..4q+3 for vertex j.
__device__ float4 g_X4[6 * NVTX];
// Partial lx: [jh][row][12] f32x2 pairs (pair p = channels 2p, 2p+1).
__device__ ull g_part[2 * NVTX * 12];
// Zero-filled landing pad for OOB prefetch addresses (never written).
__device__ float4 g_zero4[32];

#define FFMA2(d, a, b) asm("fma.rn.f32x2 %0, %1, %2, %0;" : "+l"(d) : "l"(a), "l"(b))
#define FADD2(d, a, b) asm("add.rn.f32x2 %0, %1, %2;" : "=l"(d) : "l"(a), "l"(b))
#define PACK2(d, f)    asm("mov.b64 %0, {%1, %1};"     : "=l"(d) : "f"(f))

// ---------------------------------------------------------------------------
// Kernel 0: repack x[8][NV][3] -> g_X4[c/4][j].{c%4}
// ---------------------------------------------------------------------------
__global__ void k_buildx(const float* __restrict__ x) {
    int idx = blockIdx.x * blockDim.x + threadIdx.x;   // over NV*24
    if (idx >= NVTX * NCH) return;
    int j = idx / NCH;
    int c = idx - j * NCH;
    int b = c / 3;
    int k = c - 3 * b;
    float v = x[(b * NVTX + j) * 3 + k];
    reinterpret_cast<float*>(g_X4)[(c >> 2) * (NVTX * 4) + j * 4 + (c & 3)] = v;
}

// ---------------------------------------------------------------------------
// Kernel 1: main stream. grid = (NRB, 2), block = 256.
//   Each warp owns 4 rows; each lane owns a float4 (4 consecutive j) per step.
// ---------------------------------------------------------------------------
__global__ void __launch_bounds__(256) k_main(const float* __restrict__ L) {
    // Xs[quad][j%4][j/4] so lane-indexed reads (j/4 == lane-contiguous) are
    // conflict-free LDS.128.
    __shared__ float4 Xs[6][4][JT / 4];

    const int tid  = threadIdx.x;
    const int lane = tid & 31;
    const int warp = tid >> 5;
    const int jh   = blockIdx.y;
    const int row0 = blockIdx.x * ROWS_CTA + warp * RPW;
    const int jbeg = jh * JHALF;

    ull acc[RPW][12];
#pragma unroll
    for (int r = 0; r < RPW; r++)
#pragma unroll
        for (int p = 0; p < 12; p++) acc[r][p] = 0ULL;

    // row-clamped L row base pointers (OOB rows guarded at store time)
    const float* Lrow[RPW];
#pragma unroll
    for (int r = 0; r < RPW; r++) {
        int rr = row0 + r;
        if (rr >= NVTX) rr = NVTX - 1;
        Lrow[r] = L + (size_t)rr * NVTX + jbeg;
    }

    const float4* const pz = g_zero4 + lane;

    // depth-PD register pipeline of L (steps of 128 j); first PD steps in-range
    float4 Lpre[PD][RPW];
#pragma unroll
    for (int q = 0; q < PD; q++) {
        int col = q * 128 + lane * 4;
#pragma unroll
        for (int r = 0; r < RPW; r++)
            Lpre[q][r] = __ldcs(reinterpret_cast<const float4*>(Lrow[r] + col));
    }

    int gs = 0;
    for (int t = 0; t < NTILES; t++) {
        // stage X tile (zero-padded past JHALF), swizzled layout
        for (int idx = tid; idx < 6 * JT; idx += 256) {
            int p4 = idx >> 9;          // idx / JT
            int jl = idx & (JT - 1);
            int jgl = t * JT + jl;
            float4 v = make_float4(0.f, 0.f, 0.f, 0.f);
            if (jgl < JHALF) v = __ldg(&g_X4[p4 * NVTX + jbeg + jgl]);
            Xs[p4][jl & 3][jl >> 2] = v;
        }
        __syncthreads();

#pragma unroll
        for (int s = 0; s < JT / 128; s++, gs++) {
            const int buf = gs & (PD - 1);

            // snapshot current values (slot is refilled below)
            float curf[RPW][4];
#pragma unroll
            for (int r = 0; r < RPW; r++) {
                float4 c4 = Lpre[buf][r];
                curf[r][0] = c4.x; curf[r][1] = c4.y;
                curf[r][2] = c4.z; curf[r][3] = c4.w;
            }

            // prefetch step gs+PD: select on ADDRESS (no load-result select)
            {
                int col = (gs + PD) * 128 + lane * 4;
                bool ok = (col < JHALF);
#pragma unroll
                for (int r = 0; r < RPW; r++) {
                    const float4* p = ok
                        ? reinterpret_cast<const float4*>(Lrow[r] + col) : pz;
                    Lpre[buf][r] = __ldcs(p);
                }
            }

            // zero tests: per-jj column union across the 4 rows
            unsigned u[4];
#pragma unroll
            for (int jj = 0; jj < 4; jj++)
                u[jj] = __float_as_uint(curf[0][jj]) | __float_as_uint(curf[1][jj])
                      | __float_as_uint(curf[2][jj]) | __float_as_uint(curf[3][jj]);
            unsigned uu = u[0] | u[1] | u[2] | u[3];

            if (__ballot_sync(0xffffffffu, uu != 0)) {
                const int jq = s * 32 + lane;   // index into Xs[.][jj][.]
#pragma unroll
                for (int jj = 0; jj < 4; jj++) {
                    if (__ballot_sync(0xffffffffu, u[jj] != 0)) {
                        ull a[RPW];
#pragma unroll
                        for (int r = 0; r < RPW; r++) PACK2(a[r], curf[r][jj]);
#pragma unroll
                        for (int p4 = 0; p4 < 6; p4++) {
                            ulonglong2 xv = *reinterpret_cast<const ulonglong2*>(
                                &Xs[p4][jj][jq]);
#pragma unroll
                            for (int r = 0; r < RPW; r++) {
                                FFMA2(acc[r][2 * p4 + 0], a[r], xv.x);
                                FFMA2(acc[r][2 * p4 + 1], a[r], xv.y);
                            }
                        }
                    }
                }
            }
        }
        __syncthreads();
    }

    // lane-reduce each (row, pair) across the warp (butterfly, f32x2 adds)
#pragma unroll
    for (int r = 0; r < RPW; r++) {
#pragma unroll
        for (int p = 0; p < 12; p++) {
            ull v = acc[r][p];
#pragma unroll
            for (int m = 16; m >= 1; m >>= 1) {
                ull o = __shfl_xor_sync(0xffffffffu, v, m);
                ull s;
                FADD2(s, v, o);
                v = s;
            }
            acc[r][p] = v;
        }
    }

    if (lane == 0) {
#pragma unroll
        for (int r = 0; r < RPW; r++) {
            int row = row0 + r;
            if (row < NVTX) {
#pragma unroll
                for (int p = 0; p < 12; p++)
                    g_part[((size_t)jh * NVTX + row) * 12 + p] = acc[r][p];
            }
        }
    }
}

// ---------------------------------------------------------------------------
// Kernel 2: finalize. One block per batch.
// ---------------------------------------------------------------------------
__global__ void k_fin(const float* __restrict__ w, float* __restrict__ out) {
    const int b = blockIdx.x;
    const int tid = threadIdx.x;
    __shared__ float red[256];

    const float* P = reinterpret_cast<const float*>(g_part); // [jh][row][24]
    float s = 0.f;
    for (int idx = tid; idx < NVTX * 3; idx += 256) {
        int i = idx / 3;
        int k = idx - 3 * i;
        int c = 3 * b + k;
        float v = P[(size_t)i * 24 + c] + P[((size_t)NVTX + i) * 24 + c];
        s += v * v;
    }
    red[tid] = s;
    __syncthreads();
    for (int off = 128; off > 0; off >>= 1) {
        if (tid < off) red[tid] += red[tid + off];
        __syncthreads();
    }
    if (tid == 0) out[b] = w[0] * (float)NVTX * sqrtf(red[0]);
}

// ---------------------------------------------------------------------------
extern "C" void kernel_launch(void* const* d_in, const int* in_sizes, int n_in,
                              void* d_out, int out_size) {
    const float* x = nullptr;
    const float* L = nullptr;
    const float* w = nullptr;
    for (int i = 0; i < n_in; i++) {
        if (in_sizes[i] == 8 * NVTX * 3)          x = (const float*)d_in[i];
        else if (in_sizes[i] == NVTX * NVTX)      L = (const float*)d_in[i];
        else if (in_sizes[i] == 1)                w = (const float*)d_in[i];
    }
    float* out = (float*)d_out;

    k_buildx<<<(NVTX * NCH + 255) / 256, 256>>>(x);
    dim3 grid(NRB, 2);
    k_main<<<grid, 256>>>(L);
    k_fin<<<8, 256>>>(w, out);
}

// round 4
// speedup vs baseline: 2.2899x; 2.2899x over previous
#include <cuda_runtime.h>
#include <cuda_bf16.h>
#include <cstdint>

// LaplacianLoss: out[b] = ||w * (L @ x[b])||_F * NV
//   L: [NV, NV] f32 (400 MB, streamed once; mesh Laplacian -> ~13 nz/row)
//   x: [8, NV, 3] f32  -> repacked to X[c][j], c = 3*b + k (24 channels)
//   out: 8 f32
//
// v4 = v2 (157us known-good) with ONE fix: prefetch OOB handled by ADDRESS
// select into a zero pad instead of a select on the load RESULT. v2's result-
// select made every step block on its own prefetch (long-scoreboard), killing
// the depth-4 pipeline. Everything else unchanged.

#define NVTX     10000
#define NCH      24            // 8 batches * 3 dims
#define JHALF    5000          // j range per grid.y slice
#define JT       256           // j tile staged in smem
#define RPW      6             // rows per warp (accumulator tile)
#define WARPS    8
#define ROWS_CTA (WARPS * RPW) // 48
#define NRB      ((NVTX + ROWS_CTA - 1) / ROWS_CTA) // 209 row blocks
#define PD       4             // prefetch depth (32-j steps)

typedef unsigned long long ull;

// X repacked as [6][NV] float4: quad q holds channels 4q..4q+3 for vertex j.
__device__ float4 g_X4[6 * NVTX];
// Partial lx: [jh][row][12] f32x2 pairs (pair p = channels 2p, 2p+1).
__device__ ull g_part[2 * NVTX * 12];
// Per-(batch, slice) partial sums.
__device__ float g_red[64];
// Zero-filled landing pad for OOB prefetch addresses (never written).
__device__ float g_zero[32];

#define FFMA2(d, a, b) asm("fma.rn.f32x2 %0, %1, %2, %0;" : "+l"(d) : "l"(a), "l"(b))
#define FADD2(d, a, b) asm("add.rn.f32x2 %0, %1, %2;" : "=l"(d) : "l"(a), "l"(b))
#define PACK2(d, f)    asm("mov.b64 %0, {%1, %1};"     : "=l"(d) : "f"(f))

// ---------------------------------------------------------------------------
// Kernel 0: repack x[8][NV][3] -> g_X4[c/4][j].{c%4}
// ---------------------------------------------------------------------------
__global__ void k_buildx(const float* __restrict__ x) {
    int idx = blockIdx.x * blockDim.x + threadIdx.x;   // over NV*24
    if (idx >= NVTX * NCH) return;
    int j = idx / NCH;
    int c = idx - j * NCH;
    int b = c / 3;
    int k = c - 3 * b;
    float v = x[(b * NVTX + j) * 3 + k];
    reinterpret_cast<float*>(g_X4)[(c >> 2) * (NVTX * 4) + j * 4 + (c & 3)] = v;
}

// ---------------------------------------------------------------------------
// Kernel 1: main streaming GEMM. grid = (NRB, 2), block = 256.
// ---------------------------------------------------------------------------
__global__ void __launch_bounds__(256) k_main(const float* __restrict__ L) {
    __shared__ float4 Xs[6][JT];

    const int tid  = threadIdx.x;
    const int lane = tid & 31;
    const int warp = tid >> 5;
    const int jh   = blockIdx.y;
    const int row0 = blockIdx.x * ROWS_CTA + warp * RPW;
    const int jbeg = jh * JHALF;

    // accumulators: 6 rows x 12 channel-pairs (f32x2)
    ull acc[RPW][12];
#pragma unroll
    for (int r = 0; r < RPW; r++)
#pragma unroll
        for (int p = 0; p < 12; p++) acc[r][p] = 0ULL;

    // per-row L base pointers (row-clamped; OOB rows guarded at store time)
    const float* Lp[RPW];
#pragma unroll
    for (int r = 0; r < RPW; r++) {
        int rr = row0 + r;
        if (rr >= NVTX) rr = NVTX - 1;
        Lp[r] = L + (size_t)rr * NVTX + jbeg + lane;
    }

    const float* const zp = g_zero + lane;   // zero pad (reads return 0.0f)

    // depth-PD software prefetch of L (steps of 32 j); first PD*32 j in-range
    float Lpre[PD][RPW];
#pragma unroll
    for (int q = 0; q < PD; q++) {
#pragma unroll
        for (int r = 0; r < RPW; r++)
            Lpre[q][r] = __ldcs(Lp[r] + q * 32);
    }

    const int ntiles = (JHALF + JT - 1) / JT;      // 20
    int gs = 0;                                    // global 32-j step index

    for (int t = 0; t < ntiles; t++) {
        // stage X tile (zero-padded past JHALF)
        {
            int jl = t * JT + tid;
            int jg = jbeg + jl;
            float4 z = make_float4(0.f, 0.f, 0.f, 0.f);
            bool ok = (jl < JHALF);
#pragma unroll
            for (int p4 = 0; p4 < 6; p4++)
                Xs[p4][tid] = ok ? __ldg(&g_X4[p4 * NVTX + jg]) : z;
        }
        __syncthreads();

#pragma unroll
        for (int s = 0; s < JT / 32; s++) {
            const int buf = gs & (PD - 1);

            // grab current values before the slot is overwritten
            float cur[RPW];
#pragma unroll
            for (int r = 0; r < RPW; r++) cur[r] = Lpre[buf][r];

            // prefetch step gs+PD: OOB handled on the ADDRESS path only.
            // The load result is not touched until consumed PD steps later.
            {
                int jq  = gs + PD;
                bool ok = (jq * 32 + lane < JHALF);
                int off = jq * 32;
#pragma unroll
                for (int r = 0; r < RPW; r++) {
                    const float* p = ok ? (Lp[r] + off) : zp;
                    Lpre[buf][r] = __ldcs(p);
                }
            }

            // warp-uniform zero test: skip the FMA block if all 192 values are 0
            unsigned u = 0;
#pragma unroll
            for (int r = 0; r < RPW; r++) u |= __float_as_uint(cur[r]);

            if (__ballot_sync(0xffffffffu, u) != 0) {
                ull a[RPW];
#pragma unroll
                for (int r = 0; r < RPW; r++) PACK2(a[r], cur[r]);

                const int xi = s * 32 + lane;
#pragma unroll
                for (int p4 = 0; p4 < 6; p4++) {
                    ulonglong2 xv = *reinterpret_cast<const ulonglong2*>(&Xs[p4][xi]);
#pragma unroll
                    for (int r = 0; r < RPW; r++) {
                        FFMA2(acc[r][2 * p4 + 0], a[r], xv.x);
                        FFMA2(acc[r][2 * p4 + 1], a[r], xv.y);
                    }
                }
            }
            gs++;
        }
        __syncthreads();
    }

    // lane-reduce each (row, pair) across the warp (butterfly, f32x2 adds)
#pragma unroll
    for (int r = 0; r < RPW; r++) {
#pragma unroll
        for (int p = 0; p < 12; p++) {
            ull v = acc[r][p];
#pragma unroll
            for (int m = 16; m >= 1; m >>= 1) {
                ull o = __shfl_xor_sync(0xffffffffu, v, m);
                ull s;
                FADD2(s, v, o);
                v = s;
            }
            acc[r][p] = v;
        }
    }

    if (lane == 0) {
#pragma unroll
        for (int r = 0; r < RPW; r++) {
            int row = row0 + r;
            if (row < NVTX) {
#pragma unroll
                for (int p = 0; p < 12; p++)
                    g_part[((size_t)jh * NVTX + row) * 12 + p] = acc[r][p];
            }
        }
    }
}

// ---------------------------------------------------------------------------
// Kernel 2: partial sum-of-squares. grid = 64 (8 batches x 8 row slices).
// ---------------------------------------------------------------------------
__global__ void k_partial(void) {
    const int b  = blockIdx.x >> 3;
    const int sl = blockIdx.x & 7;
    const int tid = threadIdx.x;
    __shared__ float red[256];

    const float* P = reinterpret_cast<const float*>(g_part); // [jh][row][24]
    const int i0 = sl * (NVTX / 8);
    const int i1 = i0 + (NVTX / 8);

    float s = 0.f;
    for (int idx = i0 * 3 + tid; idx < i1 * 3; idx += 256) {
        int i = idx / 3;
        int k = idx - 3 * i;
        int c = 3 * b + k;
        float v = P[(size_t)i * 24 + c] + P[((size_t)NVTX + i) * 24 + c];
        s += v * v;
    }
    red[tid] = s;
    __syncthreads();
    for (int off = 128; off > 0; off >>= 1) {
        if (tid < off) red[tid] += red[tid + off];
        __syncthreads();
    }
    if (tid == 0) g_red[blockIdx.x] = red[0];
}

// ---------------------------------------------------------------------------
// Kernel 3: finalize. 1 block, 64 threads.
// ---------------------------------------------------------------------------
__global__ void k_final(const float* __restrict__ w, float* __restrict__ out) {
    __shared__ float sh[64];
    int t = threadIdx.x;
    sh[t] = g_red[t];
    __syncthreads();
    if (t < 8) {
        float s = 0.f;
#pragma unroll
        for (int j = 0; j < 8; j++) s += sh[t * 8 + j];
        out[t] = w[0] * (float)NVTX * sqrtf(s);
    }
}

// ---------------------------------------------------------------------------
extern "C" void kernel_launch(void* const* d_in, const int* in_sizes, int n_in,
                              void* d_out, int out_size) {
    const float* x = nullptr;
    const float* L = nullptr;
    const float* w = nullptr;
    for (int i = 0; i < n_in; i++) {
        if (in_sizes[i] == 8 * NVTX * 3)          x = (const float*)d_in[i];
        else if (in_sizes[i] == NVTX * NVTX)      L = (const float*)d_in[i];
        else if (in_sizes[i] == 1)                w = (const float*)d_in[i];
    }
    float* out = (float*)d_out;

    k_buildx<<<(NVTX * NCH + 255) / 256, 256>>>(x);
    dim3 grid(NRB, 2);
    k_main<<<grid, 256>>>(L);
    k_partial<<<64, 256>>>();
    k_final<<<1, 64>>>(w, out);
}